// round 12
// baseline (speedup 1.0000x reference)
#include <cuda_runtime.h>
#include <cstdint>

#define IMG_H 512
#define IMG_W 512
#define TILE_H 16
#define NTHREADS 128   // thread owns cols 4t..4t+3

__device__ __forceinline__ int reflr(int g) {
    g = g < 0 ? -g : g;
    if (g >= IMG_H) g = 2 * IMG_H - 2 - g;
    return g;
}

__device__ __forceinline__ uint64_t mkpolicy() {
    uint64_t pol;
    asm("createpolicy.fractional.L2::evict_last.b64 %0, 1.0;" : "=l"(pol));
    return pol;
}

__device__ __forceinline__ float2 ld2_keep(const float* p, uint64_t pol) {
    float2 v;
    asm("ld.global.nc.L2::cache_hint.v2.f32 {%0, %1}, [%2], %3;"
        : "=f"(v.x), "=f"(v.y) : "l"(p), "l"(pol));
    return v;
}
__device__ __forceinline__ float4 ld4_keep(const float* p, uint64_t pol) {
    float4 v;
    asm("ld.global.nc.L2::cache_hint.v4.f32 {%0, %1, %2, %3}, [%4], %5;"
        : "=f"(v.x), "=f"(v.y), "=f"(v.z), "=f"(v.w) : "l"(p), "l"(pol));
    return v;
}

struct Row { float2 A; float4 B; float2 C; };

// Load cols c-2..c+5 for one source row (A: c-2,c-1 | B: c..c+3 | C: c+4,c+5).
__device__ __forceinline__ Row ldrow(const float* __restrict__ rp, int c0,
                                     bool isL, bool isR, uint64_t pol)
{
    Row r;
    r.A = isL ? make_float2(0.f, 0.f) : ld2_keep(rp + c0 - 2, pol);
    r.B = ld4_keep(rp + c0, pol);
    r.C = isR ? make_float2(0.f, 0.f) : ld2_keep(rp + c0 + 4, pol);
    return r;
}

// Horizontal 5-tap sums for cols c..c+3.
// Edge renames (reflect-101): isL: (c-2,c-1)->(2,1)=(B.z,B.y);
//                             isR: (c+4,c+5)->(510,509)=(B.z,B.y).
__device__ __forceinline__ float4 hsum4(Row r, bool isL, bool isR)
{
    float2 A = r.A; float4 B = r.B; float2 C = r.C;
    if (isL) { A.x = B.z; A.y = B.y; }
    if (isR) { C.x = B.z; C.y = B.y; }
    float s = B.y + B.z;
    float4 h;
    h.x = A.x + A.y + B.x + s;
    h.y = A.y + B.x + s + B.w;
    h.z = B.x + s + B.w + C.x;
    h.w = s + B.w + C.x + C.y;
    return h;
}

__global__ __launch_bounds__(NTHREADS, 10)
void smooth5_kernel(const float* __restrict__ in, float* __restrict__ out)
{
    const int tid   = threadIdx.x;
    const int c0    = 4 * tid;
    const int plane = blockIdx.y;
    const int row0  = blockIdx.x * TILE_H;

    const float* ip = in  + (size_t)plane * (IMG_H * IMG_W);
    float*       op = out + (size_t)plane * (IMG_H * IMG_W);

    const bool isL = (tid == 0);
    const bool isR = (tid == NTHREADS - 1);
    const uint64_t pol = mkpolicy();

    // Warm-up: hsums of source rows row0-2 .. row0+1 (top reflected)
    float4 h0 = hsum4(ldrow(ip + (size_t)reflr(row0 - 2) * IMG_W, c0, isL, isR, pol), isL, isR);
    float4 h1 = hsum4(ldrow(ip + (size_t)reflr(row0 - 1) * IMG_W, c0, isL, isR, pol), isL, isR);
    float4 h2 = hsum4(ldrow(ip + (size_t)(row0)          * IMG_W, c0, isL, isR, pol), isL, isR);
    float4 h3 = hsum4(ldrow(ip + (size_t)(row0 + 1)      * IMG_W, c0, isL, isR, pol), isL, isR);

    const float inv25 = 1.0f / 25.0f;

    if (row0 + TILE_H + 2 <= IMG_H) {
        // ---------- interior fast path, 1-row software pipeline ----------
        const float* sp = ip + (size_t)(row0 + 2) * IMG_W;
        float*       dp = op + (size_t)(row0)     * IMG_W + c0;

        Row cur = ldrow(sp, c0, isL, isR, pol);
        sp += IMG_W;

        #pragma unroll
        for (int r = 0; r < TILE_H; ++r) {
            Row nxt;
            if (r < TILE_H - 1) {
                nxt = ldrow(sp, c0, isL, isR, pol);
                sp += IMG_W;
            }
            float4 h = hsum4(cur, isL, isR);
            float4 o;
            o.x = (h0.x + h1.x + h2.x + h3.x + h.x) * inv25;
            o.y = (h0.y + h1.y + h2.y + h3.y + h.y) * inv25;
            o.z = (h0.z + h1.z + h2.z + h3.z + h.z) * inv25;
            o.w = (h0.w + h1.w + h2.w + h3.w + h.w) * inv25;
            __stcs(reinterpret_cast<float4*>(dp), o);
            dp += IMG_W;
            h0 = h1; h1 = h2; h2 = h3; h3 = h;
            cur = nxt;
        }
    } else {
        // ---------- bottom tile: reflected row indexing ----------
        #pragma unroll
        for (int r = 0; r < TILE_H; ++r) {
            const float* rp = ip + (size_t)reflr(row0 + 2 + r) * IMG_W;
            float4 h = hsum4(ldrow(rp, c0, isL, isR, pol), isL, isR);
            float4 o;
            o.x = (h0.x + h1.x + h2.x + h3.x + h.x) * inv25;
            o.y = (h0.y + h1.y + h2.y + h3.y + h.y) * inv25;
            o.z = (h0.z + h1.z + h2.z + h3.z + h.z) * inv25;
            o.w = (h0.w + h1.w + h2.w + h3.w + h.w) * inv25;
            __stcs(reinterpret_cast<float4*>(op + (size_t)(row0 + r) * IMG_W + c0), o);
            h0 = h1; h1 = h2; h2 = h3; h3 = h;
        }
    }
}

extern "C" void kernel_launch(void* const* d_in, const int* in_sizes, int n_in,
                              void* d_out, int out_size)
{
    const float* in  = (const float*)d_in[0];
    float*       out = (float*)d_out;
    int planes = in_sizes[0] / (IMG_H * IMG_W);   // B*C = 96
    dim3 grid(IMG_H / TILE_H, planes);             // 32 x 96 = 3072 blocks
    smooth5_kernel<<<grid, NTHREADS>>>(in, out);
}